// round 2
// baseline (speedup 1.0000x reference)
#include <cuda_runtime.h>
#include <cuda_bf16.h>
#include <math.h>

// Problem constants
#define BATCH        16
#define NUM_HEADS    32
#define NUM_KV_HEADS 8
#define N_REP        4      // NUM_HEADS / NUM_KV_HEADS
#define HEAD_DIM     128
#define BLOCK_SIZE   16
#define BLOCKS_PER_SEQ 256
#define MAX_SEQ      4096
#define SCALE        0.08838834764831845f

// Split-KV configuration
#define PART_TOK     256
#define NPARTS       (MAX_SEQ / PART_TOK)   // 16
#define NWARPS       8
#define NTHREADS     (NWARPS * 32)          // 256

// Partial scratch (device globals: allocation-free)
// o: [B][KVH][NPARTS][N_REP][HEAD_DIM]
__device__ float g_part_o[BATCH * NUM_KV_HEADS * NPARTS * N_REP * HEAD_DIM];
// m, l: [B][KVH][NPARTS][N_REP]
__device__ float g_part_m[BATCH * NUM_KV_HEADS * NPARTS * N_REP];
__device__ float g_part_l[BATCH * NUM_KV_HEADS * NPARTS * N_REP];

// ---------------------------------------------------------------------------
// Kernel 1: scatter new K/V tokens into the caches at slot_mapping.
// k: [B, KVH, D] -> cache flat view [NUM_BLOCKS*BLOCK_SIZE, KVH, D]
// ---------------------------------------------------------------------------
__global__ void scatter_kv_kernel(const float* __restrict__ k,
                                  const float* __restrict__ v,
                                  float* __restrict__ k_cache,
                                  float* __restrict__ v_cache,
                                  const int* __restrict__ slot_mapping) {
    const int b = blockIdx.x;          // 0..15
    const int t = threadIdx.x;         // 0..1023  (KVH*D = 1024)
    const int slot = slot_mapping[b];
    const size_t dst = (size_t)slot * (NUM_KV_HEADS * HEAD_DIM) + t;
    const size_t src = (size_t)b    * (NUM_KV_HEADS * HEAD_DIM) + t;
    k_cache[dst] = k[src];
    v_cache[dst] = v[src];
}

// ---------------------------------------------------------------------------
// Kernel 2: split-KV attention partials.
// grid: (NPARTS, NUM_KV_HEADS, BATCH), block: 256
// ---------------------------------------------------------------------------
__global__ __launch_bounds__(NTHREADS)
void attn_partial_kernel(const float* __restrict__ q,
                         const float* __restrict__ k_cache,
                         const float* __restrict__ v_cache,
                         const int* __restrict__ block_tables,
                         const int* __restrict__ context_lens) {
    const int part = blockIdx.x;
    const int g    = blockIdx.y;   // kv head
    const int b    = blockIdx.z;

    const int tid  = threadIdx.x;
    const int lane = tid & 31;
    const int w    = tid >> 5;

    const int ctx  = context_lens[b];
    const int t0   = part * PART_TOK;
    const int ntok = min(PART_TOK, ctx - t0);

    // scratch bases
    const int ml_base = ((b * NUM_KV_HEADS + g) * NPARTS + part) * N_REP;
    const int o_base  = ml_base * HEAD_DIM;

    __shared__ float s_scores[N_REP][PART_TOK];            // 4 KB
    __shared__ float s_red[NWARPS][N_REP * HEAD_DIM];      // 16 KB
    __shared__ float s_ml[N_REP][2];

    if (ntok <= 0) {
        // empty partition: write neutral partials
        for (int idx = tid; idx < N_REP * HEAD_DIM; idx += NTHREADS)
            g_part_o[o_base + idx] = 0.0f;
        if (tid < N_REP) {
            g_part_m[ml_base + tid] = -1e30f;
            g_part_l[ml_base + tid] = 0.0f;
        }
        return;
    }

    const int* btab = block_tables + b * BLOCKS_PER_SEQ;

    // Load Q for the 4 heads of this group: lane owns dims [4*lane, 4*lane+3]
    float4 q4[N_REP];
#pragma unroll
    for (int h = 0; h < N_REP; h++) {
        const float* qp = q + ((size_t)(b * NUM_HEADS + g * N_REP + h)) * HEAD_DIM;
        q4[h] = *(const float4*)(qp + 4 * lane);
    }

    // ---- Pass 1: scores ----
    for (int i = w; i < ntok; i += NWARPS) {
        const int tok  = t0 + i;
        const int blk  = btab[tok >> 4];
        const float* kp = k_cache +
            (((size_t)(blk * BLOCK_SIZE + (tok & 15))) * NUM_KV_HEADS + g) * HEAD_DIM;
        const float4 k4 = *(const float4*)(kp + 4 * lane);

        float d0 = q4[0].x * k4.x + q4[0].y * k4.y + q4[0].z * k4.z + q4[0].w * k4.w;
        float d1 = q4[1].x * k4.x + q4[1].y * k4.y + q4[1].z * k4.z + q4[1].w * k4.w;
        float d2 = q4[2].x * k4.x + q4[2].y * k4.y + q4[2].z * k4.z + q4[2].w * k4.w;
        float d3 = q4[3].x * k4.x + q4[3].y * k4.y + q4[3].z * k4.z + q4[3].w * k4.w;
#pragma unroll
        for (int off = 16; off > 0; off >>= 1) {
            d0 += __shfl_xor_sync(0xffffffffu, d0, off);
            d1 += __shfl_xor_sync(0xffffffffu, d1, off);
            d2 += __shfl_xor_sync(0xffffffffu, d2, off);
            d3 += __shfl_xor_sync(0xffffffffu, d3, off);
        }
        if (lane < 4) {
            float sv = (lane == 0) ? d0 : (lane == 1) ? d1 : (lane == 2) ? d2 : d3;
            s_scores[lane][i] = sv * SCALE;
        }
    }
    __syncthreads();

    // ---- Softmax stats: warp h owns head h (h < 4) ----
    if (w < N_REP) {
        float mx = -1e30f;
        for (int i = lane; i < ntok; i += 32) mx = fmaxf(mx, s_scores[w][i]);
#pragma unroll
        for (int off = 16; off > 0; off >>= 1)
            mx = fmaxf(mx, __shfl_xor_sync(0xffffffffu, mx, off));
        float sum = 0.0f;
        for (int i = lane; i < ntok; i += 32) {
            float e = __expf(s_scores[w][i] - mx);
            s_scores[w][i] = e;
            sum += e;
        }
#pragma unroll
        for (int off = 16; off > 0; off >>= 1)
            sum += __shfl_xor_sync(0xffffffffu, sum, off);
        if (lane == 0) { s_ml[w][0] = mx; s_ml[w][1] = sum; }
    }
    __syncthreads();

    // ---- Pass 2: weighted V accumulation ----
    float4 o4[N_REP];
#pragma unroll
    for (int h = 0; h < N_REP; h++) o4[h] = make_float4(0.f, 0.f, 0.f, 0.f);

    for (int i = w; i < ntok; i += NWARPS) {
        const int tok  = t0 + i;
        const int blk  = btab[tok >> 4];
        const float* vp = v_cache +
            (((size_t)(blk * BLOCK_SIZE + (tok & 15))) * NUM_KV_HEADS + g) * HEAD_DIM;
        const float4 v4 = *(const float4*)(vp + 4 * lane);
#pragma unroll
        for (int h = 0; h < N_REP; h++) {
            const float p = s_scores[h][i];
            o4[h].x += p * v4.x;
            o4[h].y += p * v4.y;
            o4[h].z += p * v4.z;
            o4[h].w += p * v4.w;
        }
    }

    // cross-warp reduce via smem
#pragma unroll
    for (int h = 0; h < N_REP; h++)
        ((float4*)&s_red[w][h * HEAD_DIM])[lane] = o4[h];
    __syncthreads();

    for (int idx = tid; idx < N_REP * HEAD_DIM; idx += NTHREADS) {
        float acc = 0.0f;
#pragma unroll
        for (int ww = 0; ww < NWARPS; ww++) acc += s_red[ww][idx];
        g_part_o[o_base + idx] = acc;
    }
    if (tid < N_REP) {
        g_part_m[ml_base + tid] = s_ml[tid][0];
        g_part_l[ml_base + tid] = s_ml[tid][1];
    }
}

// ---------------------------------------------------------------------------
// Kernel 3: combine partials across partitions.
// grid: BATCH*NUM_HEADS blocks, 128 threads (one per dim)
// ---------------------------------------------------------------------------
__global__ __launch_bounds__(HEAD_DIM)
void attn_reduce_kernel(float* __restrict__ out) {
    const int bh = blockIdx.x;
    const int b  = bh >> 5;          // / NUM_HEADS
    const int h  = bh & 31;
    const int g  = h >> 2;           // / N_REP
    const int r  = h & 3;
    const int d  = threadIdx.x;

    const int base = (b * NUM_KV_HEADS + g) * NPARTS;   // partition base index

    float mv[NPARTS];
    float M = -1e30f;
#pragma unroll
    for (int p = 0; p < NPARTS; p++) {
        mv[p] = g_part_m[(base + p) * N_REP + r];
        M = fmaxf(M, mv[p]);
    }

    float L = 0.0f, acc = 0.0f;
#pragma unroll
    for (int p = 0; p < NPARTS; p++) {
        const float wgt = __expf(mv[p] - M);
        L   += wgt * g_part_l[(base + p) * N_REP + r];
        acc += wgt * g_part_o[((base + p) * N_REP + r) * HEAD_DIM + d];
    }

    out[((size_t)(b * NUM_HEADS + h)) * HEAD_DIM + d] = acc / L;
}

// ---------------------------------------------------------------------------
extern "C" void kernel_launch(void* const* d_in, const int* in_sizes, int n_in,
                              void* d_out, int out_size) {
    const float* q            = (const float*)d_in[0];
    const float* k            = (const float*)d_in[1];
    const float* v            = (const float*)d_in[2];
    float*       k_cache      = (float*)d_in[3];
    float*       v_cache      = (float*)d_in[4];
    const int*   block_tables = (const int*)d_in[5];
    const int*   context_lens = (const int*)d_in[6];
    const int*   slot_mapping = (const int*)d_in[7];
    float*       out          = (float*)d_out;

    scatter_kv_kernel<<<BATCH, NUM_KV_HEADS * HEAD_DIM>>>(
        k, v, k_cache, v_cache, slot_mapping);

    dim3 grid(NPARTS, NUM_KV_HEADS, BATCH);
    attn_partial_kernel<<<grid, NTHREADS>>>(
        q, k_cache, v_cache, block_tables, context_lens);

    attn_reduce_kernel<<<BATCH * NUM_HEADS, HEAD_DIM>>>(out);
}

// round 4
// speedup vs baseline: 1.1108x; 1.1108x over previous
#include <cuda_runtime.h>
#include <cuda_bf16.h>
#include <math.h>

// Problem constants
#define BATCH        16
#define NUM_HEADS    32
#define NUM_KV_HEADS 8
#define N_REP        4      // NUM_HEADS / NUM_KV_HEADS
#define HEAD_DIM     128
#define BLOCK_SIZE   16
#define BLOCKS_PER_SEQ 256
#define MAX_SEQ      4096
#define SCALE        0.08838834764831845f

// Split-KV configuration
#define PART_TOK     256
#define NPARTS       (MAX_SEQ / PART_TOK)   // 16
#define NWARPS       8
#define NTHREADS     (NWARPS * 32)          // 256
#define BLOCKS_PER_PART (PART_TOK / BLOCK_SIZE)  // 16

// Partial scratch (device globals: allocation-free)
// o: [B][KVH][NPARTS][N_REP][HEAD_DIM] (unnormalized)
__device__ float g_part_o[BATCH * NUM_KV_HEADS * NPARTS * N_REP * HEAD_DIM];
// m, l: [B][KVH][NPARTS][N_REP]
__device__ float g_part_m[BATCH * NUM_KV_HEADS * NPARTS * N_REP];
__device__ float g_part_l[BATCH * NUM_KV_HEADS * NPARTS * N_REP];

// ---------------------------------------------------------------------------
// Kernel 1: scatter new K/V tokens into the caches at slot_mapping (float4).
// ---------------------------------------------------------------------------
__global__ void scatter_kv_kernel(const float4* __restrict__ k,
                                  const float4* __restrict__ v,
                                  float4* __restrict__ k_cache,
                                  float4* __restrict__ v_cache,
                                  const int* __restrict__ slot_mapping) {
    const int b = blockIdx.x;          // 0..15
    const int t = threadIdx.x;         // 0..255  (KVH*D/4 = 256 float4)
    const int slot = slot_mapping[b];
    const size_t dst = (size_t)slot * (NUM_KV_HEADS * HEAD_DIM / 4) + t;
    const size_t src = (size_t)b    * (NUM_KV_HEADS * HEAD_DIM / 4) + t;
    k_cache[dst] = k[src];
    v_cache[dst] = v[src];
}

// ---------------------------------------------------------------------------
// Kernel 2: split-KV attention partials, single fused pass with online softmax.
// grid: (NPARTS, NUM_KV_HEADS, BATCH), block: 256
// ---------------------------------------------------------------------------
__global__ __launch_bounds__(NTHREADS)
void attn_partial_kernel(const float* __restrict__ q,
                         const float* __restrict__ k_cache,
                         const float* __restrict__ v_cache,
                         const int* __restrict__ block_tables,
                         const int* __restrict__ context_lens) {
    const int part = blockIdx.x;
    const int g    = blockIdx.y;   // kv head
    const int b    = blockIdx.z;

    const int tid  = threadIdx.x;
    const int lane = tid & 31;
    const int w    = tid >> 5;

    const int ctx  = context_lens[b];
    const int t0   = part * PART_TOK;
    const int ntok = min(PART_TOK, ctx - t0);
    if (ntok <= 0) return;   // reduce kernel knows which partitions are valid

    __shared__ int   s_blk[BLOCKS_PER_PART];
    __shared__ float s_m[NWARPS][N_REP];
    __shared__ float s_l[NWARPS][N_REP];
    __shared__ float s_scale[NWARPS][N_REP];
    __shared__ float s_M[N_REP];
    __shared__ float s_red[NWARPS][N_REP * HEAD_DIM];   // 16 KB

    // Cache this partition's block-table entries
    if (tid < BLOCKS_PER_PART)
        s_blk[tid] = block_tables[b * BLOCKS_PER_SEQ + part * BLOCKS_PER_PART + tid];
    __syncthreads();

    // Load Q for the 4 heads of this group: lane owns dims [4*lane, 4*lane+3]
    float4 q4[N_REP];
#pragma unroll
    for (int h = 0; h < N_REP; h++) {
        const float* qp = q + ((size_t)(b * NUM_HEADS + g * N_REP + h)) * HEAD_DIM;
        q4[h] = *(const float4*)(qp + 4 * lane);
    }

    // Online-softmax running state (per warp, per head)
    float  m[N_REP], l[N_REP];
    float4 o4[N_REP];
#pragma unroll
    for (int h = 0; h < N_REP; h++) {
        m[h] = -1e30f; l[h] = 0.0f;
        o4[h] = make_float4(0.f, 0.f, 0.f, 0.f);
    }

    // ---- Fused single pass over tokens with 1-stage software pipeline ----
    int i = w;
    float4 k4, v4;
    if (i < ntok) {
        const int blk = s_blk[i >> 4];
        const size_t base =
            (((size_t)(blk * BLOCK_SIZE + ((t0 + i) & 15))) * NUM_KV_HEADS + g) * HEAD_DIM
            + 4 * lane;
        k4 = *(const float4*)(k_cache + base);
        v4 = *(const float4*)(v_cache + base);
    }

    while (i < ntok) {
        const int inext = i + NWARPS;
        float4 kn, vn;
        if (inext < ntok) {
            const int blk = s_blk[inext >> 4];
            const size_t base =
                (((size_t)(blk * BLOCK_SIZE + ((t0 + inext) & 15))) * NUM_KV_HEADS + g) * HEAD_DIM
                + 4 * lane;
            kn = *(const float4*)(k_cache + base);
            vn = *(const float4*)(v_cache + base);
        }

        // dots for the 4 heads
        float d0 = q4[0].x * k4.x + q4[0].y * k4.y + q4[0].z * k4.z + q4[0].w * k4.w;
        float d1 = q4[1].x * k4.x + q4[1].y * k4.y + q4[1].z * k4.z + q4[1].w * k4.w;
        float d2 = q4[2].x * k4.x + q4[2].y * k4.y + q4[2].z * k4.z + q4[2].w * k4.w;
        float d3 = q4[3].x * k4.x + q4[3].y * k4.y + q4[3].z * k4.z + q4[3].w * k4.w;
#pragma unroll
        for (int off = 16; off > 0; off >>= 1) {
            d0 += __shfl_xor_sync(0xffffffffu, d0, off);
            d1 += __shfl_xor_sync(0xffffffffu, d1, off);
            d2 += __shfl_xor_sync(0xffffffffu, d2, off);
            d3 += __shfl_xor_sync(0xffffffffu, d3, off);
        }
        float s[N_REP];
        s[0] = d0 * SCALE; s[1] = d1 * SCALE; s[2] = d2 * SCALE; s[3] = d3 * SCALE;

#pragma unroll
        for (int h = 0; h < N_REP; h++) {
            const float mn   = fmaxf(m[h], s[h]);
            const float corr = __expf(m[h] - mn);   // ==1 when max unchanged
            const float p    = __expf(s[h] - mn);
            m[h] = mn;
            l[h] = l[h] * corr + p;
            o4[h].x = o4[h].x * corr + p * v4.x;
            o4[h].y = o4[h].y * corr + p * v4.y;
            o4[h].z = o4[h].z * corr + p * v4.z;
            o4[h].w = o4[h].w * corr + p * v4.w;
        }

        k4 = kn; v4 = vn; i = inext;
    }

    // ---- Per-warp partials -> smem ----
#pragma unroll
    for (int h = 0; h < N_REP; h++)
        ((float4*)&s_red[w][h * HEAD_DIM])[lane] = o4[h];
    if (lane < N_REP) {
        s_m[w][lane] = m[lane];
        s_l[w][lane] = l[lane];
    }
    __syncthreads();

    const int ml_base = ((b * NUM_KV_HEADS + g) * NPARTS + part) * N_REP;
    const int o_base  = ml_base * HEAD_DIM;

    // Merge stats across warps (threads 0..3, one per head)
    if (tid < N_REP) {
        float M = -1e30f;
#pragma unroll
        for (int ww = 0; ww < NWARPS; ww++) M = fmaxf(M, s_m[ww][tid]);
        float L = 0.0f;
#pragma unroll
        for (int ww = 0; ww < NWARPS; ww++)
            L += __expf(s_m[ww][tid] - M) * s_l[ww][tid];
        s_M[tid] = M;
        g_part_m[ml_base + tid] = M;
        g_part_l[ml_base + tid] = L;
    }
    __syncthreads();
    // Per-warp rescale factors
    if (tid < NWARPS * N_REP) {
        const int ww = tid >> 2, hh = tid & 3;
        s_scale[ww][hh] = __expf(s_m[ww][hh] - s_M[hh]);
    }
    __syncthreads();

    // Merge o across warps, write partial
    for (int idx = tid; idx < N_REP * HEAD_DIM; idx += NTHREADS) {
        const int hh = idx >> 7;
        float acc = 0.0f;
#pragma unroll
        for (int ww = 0; ww < NWARPS; ww++)
            acc += s_scale[ww][hh] * s_red[ww][idx];
        g_part_o[o_base + idx] = acc;
    }
}

// ---------------------------------------------------------------------------
// Kernel 3: combine valid partials across partitions.
// grid: BATCH*NUM_HEADS blocks, 128 threads (one per dim)
// ---------------------------------------------------------------------------
__global__ __launch_bounds__(HEAD_DIM)
void attn_reduce_kernel(float* __restrict__ out,
                        const int* __restrict__ context_lens) {
    const int bh = blockIdx.x;
    const int b  = bh >> 5;          // / NUM_HEADS
    const int h  = bh & 31;
    const int g  = h >> 2;           // / N_REP
    const int r  = h & 3;
    const int d  = threadIdx.x;

    const int ctx = context_lens[b];
    const int nvp = min(NPARTS, (ctx + PART_TOK - 1) / PART_TOK);  // >= 1

    const int base = (b * NUM_KV_HEADS + g) * NPARTS;

    float mv[NPARTS];
    float M = -1e30f;
    for (int p = 0; p < nvp; p++) {
        mv[p] = g_part_m[(base + p) * N_REP + r];
        M = fmaxf(M, mv[p]);
    }

    float L = 0.0f, acc = 0.0f;
    for (int p = 0; p < nvp; p++) {
        const float wgt = __expf(mv[p] - M);
        L   += wgt * g_part_l[(base + p) * N_REP + r];
        acc += wgt * g_part_o[((base + p) * N_REP + r) * HEAD_DIM + d];
    }

    out[((size_t)(b * NUM_HEADS + h)) * HEAD_DIM + d] = acc / L;
}

// ---------------------------------------------------------------------------
extern "C" void kernel_launch(void* const* d_in, const int* in_sizes, int n_in,
                              void* d_out, int out_size) {
    const float* q            = (const float*)d_in[0];
    const float* k            = (const float*)d_in[1];
    const float* v            = (const float*)d_in[2];
    float*       k_cache      = (float*)d_in[3];
    float*       v_cache      = (float*)d_in[4];
    const int*   block_tables = (const int*)d_in[5];
    const int*   context_lens = (const int*)d_in[6];
    const int*   slot_mapping = (const int*)d_in[7];
    float*       out          = (float*)d_out;

    scatter_kv_kernel<<<BATCH, 256>>>(
        (const float4*)k, (const float4*)v,
        (float4*)k_cache, (float4*)v_cache, slot_mapping);

    dim3 grid(NPARTS, NUM_KV_HEADS, BATCH);
    attn_partial_kernel<<<grid, NTHREADS>>>(
        q, k_cache, v_cache, block_tables, context_lens);

    attn_reduce_kernel<<<BATCH * NUM_HEADS, HEAD_DIM>>>(out, context_lens);
}